// round 1
// baseline (speedup 1.0000x reference)
#include <cuda_runtime.h>
#include <math.h>

#define N_PTS 65536
#define KKEY 64

// scratch (no allocations allowed)
__device__ unsigned long long g_keys[N_PTS];
__device__ unsigned long long g_cand[64 * KKEY];

// ---------------------------------------------------------------------------
// Kernel 1: per-point MLP score (batch 0 only), pack sortable 64-bit key.
// key = (float_bits(softplus) << 32) | ~n   -> descending sort == top_k order
// ---------------------------------------------------------------------------
__global__ __launch_bounds__(256) void score_kernel(
    const float* __restrict__ src,
    const float* __restrict__ W1, const float* __restrict__ b1,
    const float* __restrict__ W2, const float* __restrict__ b2,
    const float* __restrict__ Wa, const float* __restrict__ ba,
    const float* __restrict__ Wb, const float* __restrict__ bb_,
    const float* __restrict__ Wc, const float* __restrict__ bc)
{
    __shared__ float sW1[192];
    __shared__ float sb1[32];
    __shared__ float sW2[2048];
    __shared__ float sb2[64];
    __shared__ float sWa[1024];
    __shared__ float sba[16];
    __shared__ float sWb[128];
    __shared__ float sbb[8];
    __shared__ float sWc[8];
    __shared__ float sbc;

    const int t = threadIdx.x;
    for (int i = t; i < 192;  i += 256) sW1[i] = W1[i];
    for (int i = t; i < 2048; i += 256) sW2[i] = W2[i];
    for (int i = t; i < 1024; i += 256) sWa[i] = Wa[i];
    if (t < 128) sWb[t] = Wb[t];
    if (t < 64)  sb2[t] = b2[t];
    if (t < 32)  sb1[t] = b1[t];
    if (t < 16)  sba[t] = ba[t];
    if (t < 8)   sbb[t] = bb_[t];
    if (t < 8)   sWc[t] = Wc[t];
    if (t == 0)  sbc = bc[0];
    __syncthreads();

    const int n = blockIdx.x * 256 + t;

    float x[6];
#pragma unroll
    for (int c = 0; c < 6; c++) x[c] = src[c * N_PTS + n];

    // layer 1: 6 -> 32, relu
    float h1[32];
#pragma unroll
    for (int i = 0; i < 32; i++) {
        float v = sb1[i];
#pragma unroll
        for (int c = 0; c < 6; c++) v = fmaf(sW1[i * 6 + c], x[c], v);
        h1[i] = fmaxf(v, 0.0f);
    }

    // layer 2 (32 -> 64, relu) fused with layer a (64 -> 16) accumulation
    float a[16];
#pragma unroll
    for (int i = 0; i < 16; i++) a[i] = sba[i];

#pragma unroll 4
    for (int j = 0; j < 64; j++) {
        float v = sb2[j];
#pragma unroll
        for (int k = 0; k < 32; k++) v = fmaf(sW2[j * 32 + k], h1[k], v);
        v = fmaxf(v, 0.0f);
#pragma unroll
        for (int i = 0; i < 16; i++) a[i] = fmaf(sWa[i * 64 + j], v, a[i]);
    }
#pragma unroll
    for (int i = 0; i < 16; i++) a[i] = fmaxf(a[i], 0.0f);

    // layer b: 16 -> 8, relu
    float hb[8];
#pragma unroll
    for (int i = 0; i < 8; i++) {
        float v = sbb[i];
#pragma unroll
        for (int k = 0; k < 16; k++) v = fmaf(sWb[i * 16 + k], a[k], v);
        hb[i] = fmaxf(v, 0.0f);
    }

    // layer c: 8 -> 1, softplus (jax: logaddexp(x,0) = max(x,0)+log1p(exp(-|x|)))
    float c0 = sbc;
#pragma unroll
    for (int k = 0; k < 8; k++) c0 = fmaf(sWc[k], hb[k], c0);
    float sp = fmaxf(c0, 0.0f) + log1pf(expf(-fabsf(c0)));

    // sp > 0 always -> IEEE bits are order-monotonic as uint32
    unsigned int fb = __float_as_uint(sp);
    g_keys[n] = ((unsigned long long)fb << 32) | (unsigned int)(~n);
}

// ---------------------------------------------------------------------------
// Kernel 2: per-1024-chunk bitonic sort (descending), emit local top-64
// ---------------------------------------------------------------------------
__global__ __launch_bounds__(512) void topk_l1_kernel()
{
    __shared__ unsigned long long s[1024];
    const int t = threadIdx.x;
    const int base = blockIdx.x * 1024;

    s[t]       = g_keys[base + t];
    s[t + 512] = g_keys[base + t + 512];
    __syncthreads();

    for (int k = 2; k <= 1024; k <<= 1) {
        for (int j = k >> 1; j > 0; j >>= 1) {
#pragma unroll
            for (int ii = 0; ii < 2; ii++) {
                int i = t + ii * 512;
                int ixj = i ^ j;
                if (ixj > i) {
                    unsigned long long va = s[i], vb = s[ixj];
                    bool swap = ((i & k) == 0) ? (va < vb) : (va > vb);
                    if (swap) { s[i] = vb; s[ixj] = va; }
                }
            }
            __syncthreads();
        }
    }

    if (t < KKEY) g_cand[blockIdx.x * KKEY + t] = s[t];
}

// ---------------------------------------------------------------------------
// Kernel 3: sort 4096 candidates (descending), take top-64 indices, fused
// gather: out[b,k,c] = src_pts[b, c, idx[k]]   (B=8, C=6)
// ---------------------------------------------------------------------------
__global__ __launch_bounds__(1024) void topk_l2_gather_kernel(
    const float* __restrict__ src, float* __restrict__ out)
{
    __shared__ unsigned long long s[4096];
    const int t = threadIdx.x;

#pragma unroll
    for (int ii = 0; ii < 4; ii++) s[t + ii * 1024] = g_cand[t + ii * 1024];
    __syncthreads();

    for (int k = 2; k <= 4096; k <<= 1) {
        for (int j = k >> 1; j > 0; j >>= 1) {
#pragma unroll
            for (int ii = 0; ii < 4; ii++) {
                int i = t + ii * 1024;
                int ixj = i ^ j;
                if (ixj > i) {
                    unsigned long long va = s[i], vb = s[ixj];
                    bool swap = ((i & k) == 0) ? (va < vb) : (va > vb);
                    if (swap) { s[i] = vb; s[ixj] = va; }
                }
            }
            __syncthreads();
        }
    }

    // out shape (8, 64, 6) row-major; 3072 elements
    for (int o = t; o < 8 * KKEY * 6; o += 1024) {
        int c = o % 6;
        int k = (o / 6) % KKEY;
        int b = o / (6 * KKEY);
        int idx = (int)(~(unsigned int)s[k]);
        out[o] = src[(b * 6 + c) * N_PTS + idx];
    }
}

// ---------------------------------------------------------------------------
extern "C" void kernel_launch(void* const* d_in, const int* in_sizes, int n_in,
                              void* d_out, int out_size)
{
    const float* src = (const float*)d_in[0];   // src_pts (8,6,65536)
    // d_in[1] = tgt_pts (unused)
    const float* W1 = (const float*)d_in[2];
    const float* b1 = (const float*)d_in[3];
    const float* W2 = (const float*)d_in[4];
    const float* b2 = (const float*)d_in[5];
    const float* Wa = (const float*)d_in[6];
    const float* ba = (const float*)d_in[7];
    const float* Wb = (const float*)d_in[8];
    const float* bb = (const float*)d_in[9];
    const float* Wc = (const float*)d_in[10];
    const float* bc = (const float*)d_in[11];
    float* out = (float*)d_out;

    score_kernel<<<N_PTS / 256, 256>>>(src, W1, b1, W2, b2, Wa, ba, Wb, bb, Wc, bc);
    topk_l1_kernel<<<64, 512>>>();
    topk_l2_gather_kernel<<<1, 1024>>>(src, out);
}

// round 4
// speedup vs baseline: 1.6396x; 1.6396x over previous
#include <cuda_runtime.h>
#include <math.h>

#define N_PTS 65536
#define KKEY 64

typedef unsigned long long u64;

// scratch (no allocations allowed) — referenced ONLY from device code
__device__ u64 g_keys[N_PTS];
__device__ u64 g_cand[64 * KKEY];   // 4096
__device__ u64 g_cand2[4 * KKEY];   // 256

// ---------------------------------------------------------------------------
// Kernel 1: per-point MLP score (batch 0 only), 2 points/thread, scalar fp32.
// key = (float_bits(softplus) << 32) | ~n   -> descending sort == top_k order
// ---------------------------------------------------------------------------
#define NT_SCORE 128

__global__ __launch_bounds__(NT_SCORE) void score_kernel(
    const float* __restrict__ src,
    const float* __restrict__ W1, const float* __restrict__ b1,
    const float* __restrict__ W2, const float* __restrict__ b2,
    const float* __restrict__ Wa, const float* __restrict__ ba,
    const float* __restrict__ Wb, const float* __restrict__ bb_,
    const float* __restrict__ Wc, const float* __restrict__ bc)
{
    __shared__ float sW1[192];
    __shared__ float sW2[2048];
    __shared__ float sWa[1024];
    __shared__ float sWb[128];
    __shared__ float sWc[8];
    __shared__ float sb1[32];
    __shared__ float sb2[64];
    __shared__ float sba[16];
    __shared__ float sbb[8];
    __shared__ float sbc;

    const int t = threadIdx.x;
    for (int i = t; i < 192;  i += NT_SCORE) sW1[i] = W1[i];
    for (int i = t; i < 2048; i += NT_SCORE) sW2[i] = W2[i];
    for (int i = t; i < 1024; i += NT_SCORE) sWa[i] = Wa[i];
    if (t < 128) sWb[t] = Wb[t];
    if (t < 64)  sb2[t] = b2[t];
    if (t < 32)  sb1[t] = b1[t];
    if (t < 16)  sba[t] = ba[t];
    if (t < 8)   sbb[t] = bb_[t];
    if (t < 8)   sWc[t] = Wc[t];
    if (t == 0)  sbc = bc[0];
    __syncthreads();

    const int gid = blockIdx.x * NT_SCORE + t;   // pair id, 32768 pairs
    const int n0 = 2 * gid;                      // points n0, n0+1

    float xa[6], xb[6];
#pragma unroll
    for (int c = 0; c < 6; c++) {
        float2 v = *(const float2*)(src + c * N_PTS + n0);
        xa[c] = v.x;
        xb[c] = v.y;
    }

    // layer 1: 6 -> 32, relu (weight loaded once, feeds both points)
    float h1a[32], h1b[32];
#pragma unroll
    for (int i = 0; i < 32; i++) {
        float va = sb1[i], vb = sb1[i];
#pragma unroll
        for (int c = 0; c < 6; c++) {
            float w = sW1[i * 6 + c];
            va = fmaf(w, xa[c], va);
            vb = fmaf(w, xb[c], vb);
        }
        h1a[i] = fmaxf(va, 0.0f);
        h1b[i] = fmaxf(vb, 0.0f);
    }

    // layer 2 (32 -> 64, relu) fused with layer a (64 -> 16) accumulation
    float aa[16], ab[16];
#pragma unroll
    for (int i = 0; i < 16; i++) { aa[i] = sba[i]; ab[i] = sba[i]; }

#pragma unroll 2
    for (int j = 0; j < 64; j++) {
        // 2-way split accumulators to break the dependency chain
        float va0 = sb2[j], va1 = 0.0f;
        float vb0 = sb2[j], vb1 = 0.0f;
#pragma unroll
        for (int k = 0; k < 32; k += 2) {
            float w0 = sW2[j * 32 + k];
            float w1 = sW2[j * 32 + k + 1];
            va0 = fmaf(w0, h1a[k],     va0);
            va1 = fmaf(w1, h1a[k + 1], va1);
            vb0 = fmaf(w0, h1b[k],     vb0);
            vb1 = fmaf(w1, h1b[k + 1], vb1);
        }
        float va = fmaxf(va0 + va1, 0.0f);
        float vb = fmaxf(vb0 + vb1, 0.0f);
#pragma unroll
        for (int i = 0; i < 16; i++) {
            float w = sWa[i * 64 + j];
            aa[i] = fmaf(w, va, aa[i]);
            ab[i] = fmaf(w, vb, ab[i]);
        }
    }
#pragma unroll
    for (int i = 0; i < 16; i++) {
        aa[i] = fmaxf(aa[i], 0.0f);
        ab[i] = fmaxf(ab[i], 0.0f);
    }

    // layer b: 16 -> 8, relu
    float hba[8], hbb[8];
#pragma unroll
    for (int i = 0; i < 8; i++) {
        float va = sbb[i], vb = sbb[i];
#pragma unroll
        for (int k = 0; k < 16; k++) {
            float w = sWb[i * 16 + k];
            va = fmaf(w, aa[k], va);
            vb = fmaf(w, ab[k], vb);
        }
        hba[i] = fmaxf(va, 0.0f);
        hbb[i] = fmaxf(vb, 0.0f);
    }

    // layer c: 8 -> 1, softplus = max(x,0)+log1p(exp(-|x|))
    float c0 = sbc, c1 = sbc;
#pragma unroll
    for (int k = 0; k < 8; k++) {
        float w = sWc[k];
        c0 = fmaf(w, hba[k], c0);
        c1 = fmaf(w, hbb[k], c1);
    }
    float sp0 = fmaxf(c0, 0.0f) + log1pf(expf(-fabsf(c0)));
    float sp1 = fmaxf(c1, 0.0f) + log1pf(expf(-fabsf(c1)));

    // sp > 0 -> IEEE bits order-monotonic as uint32
    g_keys[n0]     = ((u64)__float_as_uint(sp0) << 32) | (unsigned int)(~n0);
    g_keys[n0 + 1] = ((u64)__float_as_uint(sp1) << 32) | (unsigned int)(~(n0 + 1));
}

// ---------------------------------------------------------------------------
// Hierarchical top-64: per-block bitonic sort of 1024 (descending), emit
// local top-64. STAGE selects the device globals INSIDE device code — no
// host-side device-symbol addresses (that was the R2/R3 bug).
// ---------------------------------------------------------------------------
template<int STAGE>
__global__ __launch_bounds__(512) void topk_stage_kernel()
{
    __shared__ u64 s[1024];
    const int t = threadIdx.x;

    const u64* in  = (STAGE == 0) ? g_keys : g_cand;
    u64*       out = (STAGE == 0) ? g_cand : g_cand2;
    const u64* p = in + blockIdx.x * 1024;

    s[t]       = p[t];
    s[t + 512] = p[t + 512];
    __syncthreads();

    for (int k = 2; k <= 1024; k <<= 1) {
        for (int j = k >> 1; j > 0; j >>= 1) {
#pragma unroll
            for (int ii = 0; ii < 2; ii++) {
                int i = t + ii * 512;
                int ixj = i ^ j;
                if (ixj > i) {
                    u64 va = s[i], vb = s[ixj];
                    bool sw = ((i & k) == 0) ? (va < vb) : (va > vb);
                    if (sw) { s[i] = vb; s[ixj] = va; }
                }
            }
            __syncthreads();
        }
    }

    if (t < KKEY) out[blockIdx.x * KKEY + t] = s[t];
}

// ---------------------------------------------------------------------------
// Final: sort 256 candidates (descending), fused gather
// out[b,k,c] = src_pts[b, c, idx[k]]   (B=8, K=64, C=6)
// ---------------------------------------------------------------------------
__global__ __launch_bounds__(256) void final_kernel(
    const float* __restrict__ src, float* __restrict__ out)
{
    __shared__ u64 s[256];
    const int t = threadIdx.x;
    s[t] = g_cand2[t];
    __syncthreads();

    for (int k = 2; k <= 256; k <<= 1) {
        for (int j = k >> 1; j > 0; j >>= 1) {
            int ixj = t ^ j;
            if (ixj > t) {
                u64 va = s[t], vb = s[ixj];
                bool sw = ((t & k) == 0) ? (va < vb) : (va > vb);
                if (sw) { s[t] = vb; s[ixj] = va; }
            }
            __syncthreads();
        }
    }

    // out shape (8, 64, 6) row-major; 3072 elements
#pragma unroll
    for (int o = t; o < 8 * KKEY * 6; o += 256) {
        int c = o % 6;
        int k = (o / 6) & (KKEY - 1);
        int b = o / (6 * KKEY);
        int idx = (int)(~(unsigned int)s[k]);
        out[o] = src[(b * 6 + c) * N_PTS + idx];
    }
}

// ---------------------------------------------------------------------------
extern "C" void kernel_launch(void* const* d_in, const int* in_sizes, int n_in,
                              void* d_out, int out_size)
{
    const float* src = (const float*)d_in[0];   // src_pts (8,6,65536)
    // d_in[1] = tgt_pts (unused)
    const float* W1 = (const float*)d_in[2];
    const float* b1 = (const float*)d_in[3];
    const float* W2 = (const float*)d_in[4];
    const float* b2 = (const float*)d_in[5];
    const float* Wa = (const float*)d_in[6];
    const float* ba = (const float*)d_in[7];
    const float* Wb = (const float*)d_in[8];
    const float* bb = (const float*)d_in[9];
    const float* Wc = (const float*)d_in[10];
    const float* bc = (const float*)d_in[11];
    float* out = (float*)d_out;

    score_kernel<<<N_PTS / 2 / NT_SCORE, NT_SCORE>>>(
        src, W1, b1, W2, b2, Wa, ba, Wb, bb, Wc, bc);
    topk_stage_kernel<0><<<64, 512>>>();   // 65536 -> 4096
    topk_stage_kernel<1><<<4, 512>>>();    // 4096  -> 256
    final_kernel<<<1, 256>>>(src, out);
}

// round 5
// speedup vs baseline: 1.7128x; 1.0446x over previous
#include <cuda_runtime.h>
#include <math.h>

#define N_PTS 65536
#define KKEY 64

typedef unsigned long long u64;

// scratch (no allocations allowed) — referenced ONLY from device code
__device__ u64 g_keys[N_PTS];
__device__ u64 g_cand[64 * KKEY];   // 4096
__device__ u64 g_cand2[4 * KKEY];   // 256

// ---------------------------------------------------------------------------
// packed f32x2 helpers (FFMA2: 2 fp32 FMAs per instruction, only via PTX)
// ---------------------------------------------------------------------------
__device__ __forceinline__ u64 fma2(u64 a, u64 b, u64 c) {
    u64 d;
    asm("fma.rn.f32x2 %0, %1, %2, %3;" : "=l"(d) : "l"(a), "l"(b), "l"(c));
    return d;
}
__device__ __forceinline__ u64 pack2(float lo, float hi) {
    u64 r;
    asm("mov.b64 %0, {%1, %2};" : "=l"(r) : "f"(lo), "f"(hi));
    return r;
}
__device__ __forceinline__ void unpack2(u64 x, float& lo, float& hi) {
    asm("mov.b64 {%0, %1}, %2;" : "=f"(lo), "=f"(hi) : "l"(x));
}
__device__ __forceinline__ u64 relu2(u64 x) {
    float lo, hi;
    unpack2(x, lo, hi);
    return pack2(fmaxf(lo, 0.0f), fmaxf(hi, 0.0f));
}

// ---------------------------------------------------------------------------
// Kernel 1: per-point MLP score (batch 0 only), 2 points/thread via f32x2.
// Accumulation order matches the R1-passing scalar kernel exactly ->
// bit-identical scores. key = (bits(softplus) << 32) | ~n.
// ---------------------------------------------------------------------------
#define NT_SCORE 256

__global__ __launch_bounds__(NT_SCORE) void score_kernel(
    const float* __restrict__ src,
    const float* __restrict__ W1, const float* __restrict__ b1,
    const float* __restrict__ W2, const float* __restrict__ b2,
    const float* __restrict__ Wa, const float* __restrict__ ba,
    const float* __restrict__ Wb, const float* __restrict__ bb_,
    const float* __restrict__ Wc, const float* __restrict__ bc)
{
    // weights duplicated into both f32 halves of a u64
    __shared__ u64 sW1[192];
    __shared__ u64 sW2[2048];
    __shared__ u64 sWa[1024];
    __shared__ u64 sWb[128];
    __shared__ u64 sWc[8];
    __shared__ u64 sb1[32];
    __shared__ u64 sb2[64];
    __shared__ u64 sba[16];
    __shared__ u64 sbb[8];
    __shared__ u64 sbc;

    const int t = threadIdx.x;

#define DUP(w) ( ((u64)__float_as_uint(w)) * 0x100000001ULL )
    for (int i = t; i < 2048; i += NT_SCORE) sW2[i] = DUP(W2[i]);
    for (int i = t; i < 1024; i += NT_SCORE) sWa[i] = DUP(Wa[i]);
    if (t < 192) sW1[t] = DUP(W1[t]);
    if (t < 128) sWb[t] = DUP(Wb[t]);
    if (t < 64)  sb2[t] = DUP(b2[t]);
    if (t < 32)  sb1[t] = DUP(b1[t]);
    if (t < 16)  sba[t] = DUP(ba[t]);
    if (t < 8)   sbb[t] = DUP(bb_[t]);
    if (t < 8)   sWc[t] = DUP(Wc[t]);
    if (t == 0)  sbc = DUP(bc[0]);
#undef DUP
    __syncthreads();

    const int gid = blockIdx.x * NT_SCORE + t;   // pair id, 32768 pairs
    const int n0 = 2 * gid;                      // points n0, n0+1

    u64 x[6];
#pragma unroll
    for (int c = 0; c < 6; c++) {
        float2 v = *(const float2*)(src + c * N_PTS + n0);
        x[c] = pack2(v.x, v.y);
    }

    // layer 1: 6 -> 32, relu
    u64 h1[32];
#pragma unroll
    for (int i = 0; i < 32; i++) {
        u64 v = sb1[i];
#pragma unroll
        for (int c = 0; c < 6; c++) v = fma2(sW1[i * 6 + c], x[c], v);
        h1[i] = relu2(v);
    }

    // layer 2 (32 -> 64, relu) fused with layer a (64 -> 16) accumulation
    u64 a[16];
#pragma unroll
    for (int i = 0; i < 16; i++) a[i] = sba[i];

#pragma unroll 2
    for (int j = 0; j < 64; j++) {
        u64 v = sb2[j];
#pragma unroll
        for (int k = 0; k < 32; k++) v = fma2(sW2[j * 32 + k], h1[k], v);
        v = relu2(v);
#pragma unroll
        for (int i = 0; i < 16; i++) a[i] = fma2(sWa[i * 64 + j], v, a[i]);
    }
#pragma unroll
    for (int i = 0; i < 16; i++) a[i] = relu2(a[i]);

    // layer b: 16 -> 8, relu
    u64 hb[8];
#pragma unroll
    for (int i = 0; i < 8; i++) {
        u64 v = sbb[i];
#pragma unroll
        for (int k = 0; k < 16; k++) v = fma2(sWb[i * 16 + k], a[k], v);
        hb[i] = relu2(v);
    }

    // layer c: 8 -> 1, softplus = max(x,0)+log1p(exp(-|x|))
    u64 c2 = sbc;
#pragma unroll
    for (int k = 0; k < 8; k++) c2 = fma2(sWc[k], hb[k], c2);
    float c0, c1;
    unpack2(c2, c0, c1);
    float sp0 = fmaxf(c0, 0.0f) + log1pf(expf(-fabsf(c0)));
    float sp1 = fmaxf(c1, 0.0f) + log1pf(expf(-fabsf(c1)));

    // sp > 0 -> IEEE bits order-monotonic as uint32
    ulonglong2 kk;
    kk.x = ((u64)__float_as_uint(sp0) << 32) | (unsigned int)(~n0);
    kk.y = ((u64)__float_as_uint(sp1) << 32) | (unsigned int)(~(n0 + 1));
    *(ulonglong2*)&g_keys[n0] = kk;
}

// ---------------------------------------------------------------------------
// Hierarchical top-64: per-block bitonic sort of 1024 (descending), emit
// local top-64. STAGE selects device globals INSIDE device code.
// ---------------------------------------------------------------------------
template<int STAGE>
__global__ __launch_bounds__(512) void topk_stage_kernel()
{
    __shared__ u64 s[1024];
    const int t = threadIdx.x;

    const u64* in  = (STAGE == 0) ? g_keys : g_cand;
    u64*       out = (STAGE == 0) ? g_cand : g_cand2;
    const u64* p = in + blockIdx.x * 1024;

    s[t]       = p[t];
    s[t + 512] = p[t + 512];
    __syncthreads();

    for (int k = 2; k <= 1024; k <<= 1) {
        for (int j = k >> 1; j > 0; j >>= 1) {
#pragma unroll
            for (int ii = 0; ii < 2; ii++) {
                int i = t + ii * 512;
                int ixj = i ^ j;
                if (ixj > i) {
                    u64 va = s[i], vb = s[ixj];
                    bool sw = ((i & k) == 0) ? (va < vb) : (va > vb);
                    if (sw) { s[i] = vb; s[ixj] = va; }
                }
            }
            __syncthreads();
        }
    }

    if (t < KKEY) out[blockIdx.x * KKEY + t] = s[t];
}

// ---------------------------------------------------------------------------
// Final: sort 256 candidates (descending) with register-resident bitonic
// (shfl for j<32, smem only for j>=32), then fused gather.
// out[b,k,c] = src_pts[b, c, idx[k]]   (B=8, K=64, C=6)
// ---------------------------------------------------------------------------
__global__ __launch_bounds__(256) void final_kernel(
    const float* __restrict__ src, float* __restrict__ out)
{
    __shared__ u64 s[256];
    __shared__ int sidx[KKEY];
    const int t = threadIdx.x;

    u64 v = g_cand2[t];

#pragma unroll
    for (int k = 2; k <= 256; k <<= 1) {
        const bool dir_desc = ((t & k) == 0);
#pragma unroll
        for (int j = k >> 1; j > 0; j >>= 1) {
            u64 v2;
            if (j >= 32) {
                __syncthreads();
                s[t] = v;
                __syncthreads();
                v2 = s[t ^ j];
            } else {
                v2 = __shfl_xor_sync(0xffffffffu, v, j);
            }
            const bool iLow = ((t & j) == 0);
            const bool keep_max = (dir_desc == iLow);
            v = keep_max ? (v > v2 ? v : v2) : (v < v2 ? v : v2);
        }
    }

    if (t < KKEY) sidx[t] = (int)(~(unsigned int)v);
    __syncthreads();

    // out shape (8, 64, 6) row-major; 3072 elements
#pragma unroll
    for (int o = t; o < 8 * KKEY * 6; o += 256) {
        int c = o % 6;
        int k = (o / 6) & (KKEY - 1);
        int b = o / (6 * KKEY);
        out[o] = src[(b * 6 + c) * N_PTS + sidx[k]];
    }
}

// ---------------------------------------------------------------------------
extern "C" void kernel_launch(void* const* d_in, const int* in_sizes, int n_in,
                              void* d_out, int out_size)
{
    const float* src = (const float*)d_in[0];   // src_pts (8,6,65536)
    // d_in[1] = tgt_pts (unused)
    const float* W1 = (const float*)d_in[2];
    const float* b1 = (const float*)d_in[3];
    const float* W2 = (const float*)d_in[4];
    const float* b2 = (const float*)d_in[5];
    const float* Wa = (const float*)d_in[6];
    const float* ba = (const float*)d_in[7];
    const float* Wb = (const float*)d_in[8];
    const float* bb = (const float*)d_in[9];
    const float* Wc = (const float*)d_in[10];
    const float* bc = (const float*)d_in[11];
    float* out = (float*)d_out;

    score_kernel<<<N_PTS / 2 / NT_SCORE, NT_SCORE>>>(
        src, W1, b1, W2, b2, Wa, ba, Wb, bb, Wc, bc);
    topk_stage_kernel<0><<<64, 512>>>();   // 65536 -> 4096
    topk_stage_kernel<1><<<4, 512>>>();    // 4096  -> 256
    final_kernel<<<1, 256>>>(src, out);
}

// round 6
// speedup vs baseline: 2.1669x; 1.2651x over previous
#include <cuda_runtime.h>
#include <math.h>

#define N_PTS 65536
#define KKEY 64

typedef unsigned long long u64;

// scratch (no allocations allowed) — referenced ONLY from device code
__device__ u64 g_keys[N_PTS];
__device__ u64 g_cand[64 * KKEY];   // 4096
__device__ u64 g_cand2[4 * KKEY];   // 256

// ---------------------------------------------------------------------------
// packed f32x2 helpers (FFMA2: 2 fp32 FMAs per instruction, only via PTX)
// ---------------------------------------------------------------------------
__device__ __forceinline__ u64 fma2(u64 a, u64 b, u64 c) {
    u64 d;
    asm("fma.rn.f32x2 %0, %1, %2, %3;" : "=l"(d) : "l"(a), "l"(b), "l"(c));
    return d;
}
__device__ __forceinline__ u64 add2(u64 a, u64 b) {
    u64 d;
    asm("add.rn.f32x2 %0, %1, %2;" : "=l"(d) : "l"(a), "l"(b));
    return d;
}
__device__ __forceinline__ u64 pack2(float lo, float hi) {
    u64 r;
    asm("mov.b64 %0, {%1, %2};" : "=l"(r) : "f"(lo), "f"(hi));
    return r;
}
__device__ __forceinline__ void unpack2(u64 x, float& lo, float& hi) {
    asm("mov.b64 {%0, %1}, %2;" : "=f"(lo), "=f"(hi) : "l"(x));
}
__device__ __forceinline__ u64 relu2(u64 x) {
    float lo, hi;
    unpack2(x, lo, hi);
    return pack2(fmaxf(lo, 0.0f), fmaxf(hi, 0.0f));
}

// ---------------------------------------------------------------------------
// Kernel 1: per-point MLP score (batch 0 only), 2 points/thread via f32x2.
// Vectorized LDS.128 weight reads + 4-way split accumulator chains.
// key = (bits(softplus) << 32) | ~n  -> descending sort == top_k order
// ---------------------------------------------------------------------------
#define NT_SCORE 256

__global__ __launch_bounds__(NT_SCORE) void score_kernel(
    const float* __restrict__ src,
    const float* __restrict__ W1, const float* __restrict__ b1,
    const float* __restrict__ W2, const float* __restrict__ b2,
    const float* __restrict__ Wa, const float* __restrict__ ba,
    const float* __restrict__ Wb, const float* __restrict__ bb_,
    const float* __restrict__ Wc, const float* __restrict__ bc)
{
    // weights duplicated into both f32 halves of a u64; Wa stored transposed
    __shared__ __align__(16) u64 sW1[192];
    __shared__ __align__(16) u64 sW2[2048];
    __shared__ __align__(16) u64 sWaT[1024];   // sWaT[j*16+i] = Wa[i*64+j]
    __shared__ __align__(16) u64 sWb[128];
    __shared__ __align__(16) u64 sWc[8];
    __shared__ u64 sb1[32];
    __shared__ u64 sb2[64];
    __shared__ u64 sba[16];
    __shared__ u64 sbb[8];
    __shared__ u64 sbc;

    const int t = threadIdx.x;

#define DUP(w) ( ((u64)__float_as_uint(w)) * 0x100000001ULL )
    for (int i = t; i < 2048; i += NT_SCORE) sW2[i] = DUP(W2[i]);
    for (int idx = t; idx < 1024; idx += NT_SCORE) {
        int j = idx >> 4, i = idx & 15;
        sWaT[idx] = DUP(Wa[i * 64 + j]);
    }
    if (t < 192) sW1[t] = DUP(W1[t]);
    if (t < 128) sWb[t] = DUP(Wb[t]);
    if (t < 64)  sb2[t] = DUP(b2[t]);
    if (t < 32)  sb1[t] = DUP(b1[t]);
    if (t < 16)  sba[t] = DUP(ba[t]);
    if (t < 8)   sbb[t] = DUP(bb_[t]);
    if (t < 8)   sWc[t] = DUP(Wc[t]);
    if (t == 0)  sbc = DUP(bc[0]);
#undef DUP
    __syncthreads();

    const int gid = blockIdx.x * NT_SCORE + t;   // pair id, 32768 pairs
    const int n0 = 2 * gid;                      // points n0, n0+1

    u64 x[6];
#pragma unroll
    for (int c = 0; c < 6; c++) {
        float2 v = *(const float2*)(src + c * N_PTS + n0);
        x[c] = pack2(v.x, v.y);
    }

    // layer 1: 6 -> 32, relu
    u64 h1[32];
#pragma unroll
    for (int i = 0; i < 32; i++) {
        const ulonglong2* w = (const ulonglong2*)(sW1 + i * 6);
        ulonglong2 p0 = w[0], p1 = w[1], p2 = w[2];
        u64 v = sb1[i];
        v = fma2(p0.x, x[0], v);
        v = fma2(p0.y, x[1], v);
        v = fma2(p1.x, x[2], v);
        v = fma2(p1.y, x[3], v);
        v = fma2(p2.x, x[4], v);
        v = fma2(p2.y, x[5], v);
        h1[i] = relu2(v);
    }

    // layer 2 (32 -> 64, relu) fused with layer a (64 -> 16) accumulation
    u64 a[16];
#pragma unroll
    for (int i = 0; i < 16; i++) a[i] = sba[i];

#pragma unroll 2
    for (int j = 0; j < 64; j++) {
        const ulonglong2* w2 = (const ulonglong2*)(sW2 + j * 32);
        u64 a0 = sb2[j], a1 = 0ULL, a2 = 0ULL, a3 = 0ULL;
#pragma unroll
        for (int k = 0; k < 32; k += 4) {
            ulonglong2 p0 = w2[k / 2];
            ulonglong2 p1 = w2[k / 2 + 1];
            a0 = fma2(p0.x, h1[k],     a0);
            a1 = fma2(p0.y, h1[k + 1], a1);
            a2 = fma2(p1.x, h1[k + 2], a2);
            a3 = fma2(p1.y, h1[k + 3], a3);
        }
        u64 v = relu2(add2(add2(a0, a1), add2(a2, a3)));

        const ulonglong2* wa = (const ulonglong2*)(sWaT + j * 16);
#pragma unroll
        for (int i = 0; i < 16; i += 2) {
            ulonglong2 p = wa[i / 2];
            a[i]     = fma2(p.x, v, a[i]);
            a[i + 1] = fma2(p.y, v, a[i + 1]);
        }
    }
#pragma unroll
    for (int i = 0; i < 16; i++) a[i] = relu2(a[i]);

    // layer b: 16 -> 8, relu (2-way split chains)
    u64 hb[8];
#pragma unroll
    for (int i = 0; i < 8; i++) {
        const ulonglong2* wb = (const ulonglong2*)(sWb + i * 16);
        u64 s0 = sbb[i], s1 = 0ULL;
#pragma unroll
        for (int k = 0; k < 16; k += 4) {
            ulonglong2 p0 = wb[k / 2];
            ulonglong2 p1 = wb[k / 2 + 1];
            s0 = fma2(p0.x, a[k],     s0);
            s1 = fma2(p0.y, a[k + 1], s1);
            s0 = fma2(p1.x, a[k + 2], s0);
            s1 = fma2(p1.y, a[k + 3], s1);
        }
        hb[i] = relu2(add2(s0, s1));
    }

    // layer c: 8 -> 1, softplus = max(x,0)+log1p(exp(-|x|))
    u64 c2 = sbc;
#pragma unroll
    for (int k = 0; k < 8; k++) c2 = fma2(sWc[k], hb[k], c2);
    float c0, c1;
    unpack2(c2, c0, c1);
    float sp0 = fmaxf(c0, 0.0f) + log1pf(expf(-fabsf(c0)));
    float sp1 = fmaxf(c1, 0.0f) + log1pf(expf(-fabsf(c1)));

    // sp > 0 -> IEEE bits order-monotonic as uint32
    ulonglong2 kk;
    kk.x = ((u64)__float_as_uint(sp0) << 32) | (unsigned int)(~n0);
    kk.y = ((u64)__float_as_uint(sp1) << 32) | (unsigned int)(~(n0 + 1));
    *(ulonglong2*)&g_keys[n0] = kk;
}

// ---------------------------------------------------------------------------
// bitonic compare-select for element at global position i, partner value pv
// (descending overall). Keys are unique (low bits = ~index).
// ---------------------------------------------------------------------------
__device__ __forceinline__ u64 cmpsel(u64 v, u64 pv, int i, int k, int j) {
    bool keep_max = (((i & k) == 0) == ((i & j) == 0));
    u64 mx = v > pv ? v : pv;
    u64 mn = v > pv ? pv : v;
    return keep_max ? mx : mn;
}

// ---------------------------------------------------------------------------
// Hierarchical top-64: per-block register/shfl bitonic sort of 1024
// (descending), 2 elems/thread (indices t and t+512). Only partner
// distances 32..256 touch smem; j<32 via shfl; j=512 in-thread.
// STAGE selects device globals INSIDE device code.
// ---------------------------------------------------------------------------
template<int STAGE>
__global__ __launch_bounds__(512) void topk_stage_kernel()
{
    __shared__ u64 s[1024];
    const int t = threadIdx.x;

    const u64* in  = (STAGE == 0) ? g_keys : g_cand;
    u64*       out = (STAGE == 0) ? g_cand : g_cand2;
    const u64* p = in + blockIdx.x * 1024;

    u64 v0 = p[t];
    u64 v1 = p[t + 512];

#pragma unroll
    for (int k = 2; k <= 1024; k <<= 1) {
#pragma unroll
        for (int j = k >> 1; j > 0; j >>= 1) {
            if (j >= 512) {
                // partner is the thread's own other element (t <-> t+512)
                bool keep_max = ((t & k) == 0);   // dir at low index t
                u64 mx = v0 > v1 ? v0 : v1;
                u64 mn = v0 > v1 ? v1 : v0;
                v0 = keep_max ? mx : mn;
                v1 = keep_max ? mn : mx;
            } else if (j >= 32) {
                __syncthreads();
                s[t] = v0;
                s[t + 512] = v1;
                __syncthreads();
                u64 p0 = s[t ^ j];
                u64 p1 = s[(t + 512) ^ j];
                v0 = cmpsel(v0, p0, t, k, j);
                v1 = cmpsel(v1, p1, t + 512, k, j);
            } else {
                u64 p0 = __shfl_xor_sync(0xffffffffu, v0, j);
                u64 p1 = __shfl_xor_sync(0xffffffffu, v1, j);
                v0 = cmpsel(v0, p0, t, k, j);
                v1 = cmpsel(v1, p1, t + 512, k, j);
            }
        }
    }

    // descending: elements 0..63 are v0 of threads 0..63
    if (t < KKEY) out[blockIdx.x * KKEY + t] = v0;
}

// ---------------------------------------------------------------------------
// Final: sort 256 candidates (descending) with register-resident bitonic
// (shfl for j<32, smem only for j>=32), then fused gather.
// out[b,k,c] = src_pts[b, c, idx[k]]   (B=8, K=64, C=6)
// ---------------------------------------------------------------------------
__global__ __launch_bounds__(256) void final_kernel(
    const float* __restrict__ src, float* __restrict__ out)
{
    __shared__ u64 s[256];
    __shared__ int sidx[KKEY];
    const int t = threadIdx.x;

    u64 v = g_cand2[t];

#pragma unroll
    for (int k = 2; k <= 256; k <<= 1) {
        const bool dir_desc = ((t & k) == 0);
#pragma unroll
        for (int j = k >> 1; j > 0; j >>= 1) {
            u64 v2;
            if (j >= 32) {
                __syncthreads();
                s[t] = v;
                __syncthreads();
                v2 = s[t ^ j];
            } else {
                v2 = __shfl_xor_sync(0xffffffffu, v, j);
            }
            const bool iLow = ((t & j) == 0);
            const bool keep_max = (dir_desc == iLow);
            v = keep_max ? (v > v2 ? v : v2) : (v < v2 ? v : v2);
        }
    }

    if (t < KKEY) sidx[t] = (int)(~(unsigned int)v);
    __syncthreads();

    // out shape (8, 64, 6) row-major; 3072 elements
#pragma unroll
    for (int o = t; o < 8 * KKEY * 6; o += 256) {
        int c = o % 6;
        int k = (o / 6) & (KKEY - 1);
        int b = o / (6 * KKEY);
        out[o] = src[(b * 6 + c) * N_PTS + sidx[k]];
    }
}

// ---------------------------------------------------------------------------
extern "C" void kernel_launch(void* const* d_in, const int* in_sizes, int n_in,
                              void* d_out, int out_size)
{
    const float* src = (const float*)d_in[0];   // src_pts (8,6,65536)
    // d_in[1] = tgt_pts (unused)
    const float* W1 = (const float*)d_in[2];
    const float* b1 = (const float*)d_in[3];
    const float* W2 = (const float*)d_in[4];
    const float* b2 = (const float*)d_in[5];
    const float* Wa = (const float*)d_in[6];
    const float* ba = (const float*)d_in[7];
    const float* Wb = (const float*)d_in[8];
    const float* bb = (const float*)d_in[9];
    const float* Wc = (const float*)d_in[10];
    const float* bc = (const float*)d_in[11];
    float* out = (float*)d_out;

    score_kernel<<<N_PTS / 2 / NT_SCORE, NT_SCORE>>>(
        src, W1, b1, W2, b2, Wa, ba, Wb, bb, Wc, bc);
    topk_stage_kernel<0><<<64, 512>>>();   // 65536 -> 4096
    topk_stage_kernel<1><<<4, 512>>>();    // 4096  -> 256
    final_kernel<<<1, 256>>>(src, out);
}